// round 1
// baseline (speedup 1.0000x reference)
#include <cuda_runtime.h>
#include <cuda_bf16.h>
#include <math.h>

// ---------------- problem constants ----------------
#define N0   120000
#define N1   12000
#define N2   1024
#define E1   300000
#define E2   10240
#define F_IN 602
#define H1   8
#define C1   8
#define HC   64        // H1*C1
#define NCLS 41
#define ET1  (E1 + N1) // edges + self loops, layer 1
#define ET2  (E2 + N2) // edges + self loops, layer 2
#define NEG_SLOPE 0.2f

// ---------------- scratch (__device__ globals; no allocs allowed) ----------------
__device__ float    g_h1[(size_t)N0 * HC];     // x @ W1
__device__ float    g_as1[(size_t)N0 * H1];    // (h * att_src1).sum(-1)
__device__ float    g_ad1[(size_t)N1 * H1];    // (h * att_dst1).sum(-1)
__device__ unsigned g_m1[(size_t)N1 * H1];     // ordered-uint segment max
__device__ float    g_s1[(size_t)N1 * H1];     // segment sum (-> reciprocal)
__device__ float    g_e1[(size_t)ET1 * H1];    // per-edge alpha / exp
__device__ int      g_src1[ET1];
__device__ int      g_dst1[ET1];
__device__ float    g_out1[(size_t)N1 * HC];   // layer-1 output (then ELU'd in place)
__device__ float    g_h2[(size_t)N1 * NCLS];   // h1 @ W2
__device__ float    g_as2[N1];
__device__ float    g_ad2[N2];
__device__ unsigned g_m2[N2];
__device__ float    g_s2[N2];
__device__ float    g_e2[ET2];
__device__ int      g_src2[ET2];
__device__ int      g_dst2[ET2];
__device__ float    g_out2[(size_t)N2 * NCLS];
__device__ int      g_is64;

// ---------------- helpers ----------------
__device__ __forceinline__ unsigned f2okey(float f) {
    unsigned u = __float_as_uint(f);
    return (u & 0x80000000u) ? ~u : (u | 0x80000000u);
}
__device__ __forceinline__ float okey2f(unsigned k) {
    return (k & 0x80000000u) ? __uint_as_float(k & 0x7FFFFFFFu)
                             : __uint_as_float(~k);
}
__device__ __forceinline__ int ldidx(const void* p, long i) {
    if (g_is64) return (int)((const long long*)p)[i];
    return ((const int*)p)[i];
}
__device__ __forceinline__ float lrelu(float x) {
    return x > 0.f ? x : NEG_SLOPE * x;
}

// ---------------- kernels ----------------

// Detect int64 vs int32 edge indices: for int64 (nonneg, LE), odd int32
// positions are all-zero high words; for int32 random indices, essentially never.
__global__ void k_detect(const int* ei) {
    int z = 0;
    #pragma unroll
    for (int j = 1; j < 64; j += 2) z |= ei[j];
    g_is64 = (z == 0) ? 1 : 0;
}

// Zero/initialize all accumulators (ordered-uint max key 0 == "below any real value",
// safe because self-loops guarantee every (dst,head) receives at least one update).
__global__ void k_zero() {
    int i = blockIdx.x * blockDim.x + threadIdx.x;
    if (i < N1 * HC)   g_out1[i] = 0.f;
    if (i < N1 * H1) { g_s1[i] = 0.f; g_m1[i] = 0u; }
    if (i < N2 * NCLS) g_out2[i] = 0.f;
    if (i < N2)      { g_s2[i] = 0.f; g_m2[i] = 0u; }
}

// GEMM1: g_h1[120000,64] = x[120000,602] @ W1[602,64].
// 64x64 tile per block, 256 threads, 4x4 per thread, packed fp32x2 FMA
// (fma.rn.f32x2, sm_100+) to double the fp32 FMA rate.
__global__ __launch_bounds__(256) void k_gemm1(const float* __restrict__ A,
                                               const float* __restrict__ B) {
    __shared__ float As[32][68];  // [k][m], padded: 68*4B keeps 16B alignment
    __shared__ float Bs[32][64];  // [k][n]
    int tid = threadIdx.x;
    int r0 = blockIdx.x * 64;
    int tx = tid & 15, ty = tid >> 4;

    unsigned long long acc[4][2];
    #pragma unroll
    for (int i = 0; i < 4; i++) { acc[i][0] = 0ull; acc[i][1] = 0ull; }

    for (int k0 = 0; k0 < F_IN; k0 += 32) {
        #pragma unroll
        for (int i = 0; i < 8; i++) {
            int e = tid + i * 256;
            int ak = e & 31, am = e >> 5;
            int gk = k0 + ak;
            As[ak][am] = (gk < F_IN) ? A[(long)(r0 + am) * F_IN + gk] : 0.f;
        }
        #pragma unroll
        for (int i = 0; i < 8; i++) {
            int e = tid + i * 256;
            int bk = e >> 6, bn = e & 63;
            int gk = k0 + bk;
            Bs[bk][bn] = (gk < F_IN) ? B[gk * HC + bn] : 0.f;
        }
        __syncthreads();
        #pragma unroll
        for (int kk = 0; kk < 32; kk++) {
            float4 av = *(const float4*)&As[kk][ty * 4];
            float4 bv = *(const float4*)&Bs[kk][tx * 4];
            unsigned long long b01, b23, a2;
            asm("mov.b64 %0,{%1,%2};" : "=l"(b01) : "f"(bv.x), "f"(bv.y));
            asm("mov.b64 %0,{%1,%2};" : "=l"(b23) : "f"(bv.z), "f"(bv.w));
            float a_[4] = {av.x, av.y, av.z, av.w};
            #pragma unroll
            for (int i = 0; i < 4; i++) {
                asm("mov.b64 %0,{%1,%1};" : "=l"(a2) : "f"(a_[i]));
                asm("fma.rn.f32x2 %0,%1,%2,%0;" : "+l"(acc[i][0]) : "l"(a2), "l"(b01));
                asm("fma.rn.f32x2 %0,%1,%2,%0;" : "+l"(acc[i][1]) : "l"(a2), "l"(b23));
            }
        }
        __syncthreads();
    }
    #pragma unroll
    for (int i = 0; i < 4; i++) {
        float4 o;
        asm("mov.b64 {%0,%1},%2;" : "=f"(o.x), "=f"(o.y) : "l"(acc[i][0]));
        asm("mov.b64 {%0,%1},%2;" : "=f"(o.z), "=f"(o.w) : "l"(acc[i][1]));
        *(float4*)&g_h1[(long)(r0 + ty * 4 + i) * HC + tx * 4] = o;
    }
}

// Per-(node,head) attention scores: a_s for all N0 nodes, a_d for nodes < N1.
__global__ void k_att1(const float* __restrict__ asrc, const float* __restrict__ adst) {
    int t = blockIdx.x * blockDim.x + threadIdx.x;
    if (t >= N0 * H1) return;
    int node = t >> 3, h = t & 7;
    const float4* hp = (const float4*)(g_h1 + (long)node * HC + h * C1);
    float4 h0 = hp[0], h4 = hp[1];
    const float4* sp = (const float4*)(asrc + h * C1);
    float4 s0 = sp[0], s4 = sp[1];
    float as = h0.x*s0.x + h0.y*s0.y + h0.z*s0.z + h0.w*s0.w
             + h4.x*s4.x + h4.y*s4.y + h4.z*s4.z + h4.w*s4.w;
    g_as1[t] = as;
    if (node < N1) {
        const float4* dp = (const float4*)(adst + h * C1);
        float4 d0 = dp[0], d4 = dp[1];
        float ad = h0.x*d0.x + h0.y*d0.y + h0.z*d0.z + h0.w*d0.w
                 + h4.x*d4.x + h4.y*d4.y + h4.z*d4.z + h4.w*d4.w;
        g_ad1[t] = ad;
    }
}

// Edge pass 1 (layer 1): decode indices once, compute leaky-relu'd alpha,
// atomic segment max.
__global__ void k_e1max(const void* __restrict__ ei) {
    int e = blockIdx.x * blockDim.x + threadIdx.x;
    if (e >= ET1) return;
    int src, dst;
    if (e < E1) { src = ldidx(ei, e); dst = ldidx(ei, (long)E1 + e); }
    else        { src = dst = e - E1; }
    g_src1[e] = src; g_dst1[e] = dst;
    const float4* sp = (const float4*)(g_as1 + (long)src * H1);
    const float4* dp = (const float4*)(g_ad1 + (long)dst * H1);
    float4 s0 = sp[0], s4 = sp[1], d0 = dp[0], d4 = dp[1];
    float a[8] = { lrelu(s0.x + d0.x), lrelu(s0.y + d0.y),
                   lrelu(s0.z + d0.z), lrelu(s0.w + d0.w),
                   lrelu(s4.x + d4.x), lrelu(s4.y + d4.y),
                   lrelu(s4.z + d4.z), lrelu(s4.w + d4.w) };
    #pragma unroll
    for (int h = 0; h < 8; h++) {
        g_e1[(long)e * H1 + h] = a[h];
        atomicMax(&g_m1[(long)dst * H1 + h], f2okey(a[h]));
    }
}

// Edge pass 2 (layer 1): e = exp(alpha - max), segment sum.
__global__ void k_e1sum() {
    int e = blockIdx.x * blockDim.x + threadIdx.x;
    if (e >= ET1) return;
    int dst = g_dst1[e];
    #pragma unroll
    for (int h = 0; h < 8; h++) {
        float m = okey2f(g_m1[(long)dst * H1 + h]);
        float ex = expf(g_e1[(long)e * H1 + h] - m);
        g_e1[(long)e * H1 + h] = ex;
        atomicAdd(&g_s1[(long)dst * H1 + h], ex);
    }
}

__global__ void k_rcp1() {
    int i = blockIdx.x * blockDim.x + threadIdx.x;
    if (i < N1 * H1) g_s1[i] = 1.f / (g_s1[i] + 1e-16f);
}

// Edge pass 3 (layer 1): weighted scatter of h_src. 16 threads/edge, float4 each.
__global__ void k_e1scat() {
    long tid = (long)blockIdx.x * blockDim.x + threadIdx.x;
    if (tid >= (long)ET1 * 16) return;
    int e = (int)(tid >> 4);
    int t = (int)(tid & 15);
    int src = g_src1[e], dst = g_dst1[e];
    int h = t >> 1;
    float w = g_e1[(long)e * H1 + h] * g_s1[(long)dst * H1 + h];
    float4 hv = *(const float4*)(g_h1 + (long)src * HC + t * 4);
    float* ob = g_out1 + (long)dst * HC + t * 4;
    atomicAdd(ob + 0, hv.x * w);
    atomicAdd(ob + 1, hv.y * w);
    atomicAdd(ob + 2, hv.z * w);
    atomicAdd(ob + 3, hv.w * w);
}

// bias + ELU in place.
__global__ void k_elu(const float* __restrict__ b1) {
    int i = blockIdx.x * blockDim.x + threadIdx.x;
    if (i >= N1 * HC) return;
    float v = g_out1[i] + b1[i & 63];
    g_out1[i] = v > 0.f ? v : expm1f(v);
}

// GEMM2: g_h2[12000,41] = elu_out[12000,64] @ W2[64,41]. W2 in smem.
__global__ __launch_bounds__(256) void k_gemm2(const float* __restrict__ W2) {
    __shared__ float Ws[HC * NCLS];
    int tid = threadIdx.x;
    for (int i = tid; i < HC * NCLS; i += 256) Ws[i] = W2[i];
    __syncthreads();
    int rbase = blockIdx.x * 32;
    for (int o = tid; o < 32 * NCLS; o += 256) {
        int r = o / NCLS, c = o - r * NCLS;
        int row = rbase + r;
        const float* hr = g_out1 + (long)row * HC;
        float acc = 0.f;
        #pragma unroll 16
        for (int k = 0; k < HC; k++) acc += hr[k] * Ws[k * NCLS + c];
        g_h2[(long)row * NCLS + c] = acc;
    }
}

__global__ void k_att2(const float* __restrict__ asrc, const float* __restrict__ adst) {
    int n = blockIdx.x * blockDim.x + threadIdx.x;
    if (n >= N1) return;
    const float* hr = g_h2 + (long)n * NCLS;
    float s = 0.f, d = 0.f;
    #pragma unroll
    for (int c = 0; c < NCLS; c++) {
        float v = hr[c];
        s += v * asrc[c];
        d += v * adst[c];
    }
    g_as2[n] = s;
    if (n < N2) g_ad2[n] = d;
}

__global__ void k_e2max(const void* __restrict__ ei) {
    int e = blockIdx.x * blockDim.x + threadIdx.x;
    if (e >= ET2) return;
    int src, dst;
    if (e < E2) { src = ldidx(ei, e); dst = ldidx(ei, (long)E2 + e); }
    else        { src = dst = e - E2; }
    g_src2[e] = src; g_dst2[e] = dst;
    float a = lrelu(g_as2[src] + g_ad2[dst]);
    g_e2[e] = a;
    atomicMax(&g_m2[dst], f2okey(a));
}

__global__ void k_e2sum() {
    int e = blockIdx.x * blockDim.x + threadIdx.x;
    if (e >= ET2) return;
    int dst = g_dst2[e];
    float ex = expf(g_e2[e] - okey2f(g_m2[dst]));
    g_e2[e] = ex;
    atomicAdd(&g_s2[dst], ex);
}

__global__ void k_rcp2() {
    int i = blockIdx.x * blockDim.x + threadIdx.x;
    if (i < N2) g_s2[i] = 1.f / (g_s2[i] + 1e-16f);
}

__global__ void k_e2scat() {
    int tid = blockIdx.x * blockDim.x + threadIdx.x;
    if (tid >= ET2 * NCLS) return;
    int e = tid / NCLS, c = tid - e * NCLS;
    int src = g_src2[e], dst = g_dst2[e];
    float w = g_e2[e] * g_s2[dst];
    atomicAdd(&g_out2[(long)dst * NCLS + c], g_h2[(long)src * NCLS + c] * w);
}

// bias + log_softmax per row, write final output.
__global__ void k_logsm(const float* __restrict__ b2, float* __restrict__ out) {
    int row = blockIdx.x;
    int t = threadIdx.x;
    __shared__ float red[64];
    float v = -3.4e38f;
    if (t < NCLS) v = g_out2[(long)row * NCLS + t] + b2[t];
    red[t] = v;
    __syncthreads();
    for (int s = 32; s > 0; s >>= 1) {
        if (t < s) red[t] = fmaxf(red[t], red[t + s]);
        __syncthreads();
    }
    float m = red[0];
    __syncthreads();
    red[t] = (t < NCLS) ? expf(v - m) : 0.f;
    __syncthreads();
    for (int s = 32; s > 0; s >>= 1) {
        if (t < s) red[t] += red[t + s];
        __syncthreads();
    }
    float lse = m + logf(red[0]);
    if (t < NCLS) out[(long)row * NCLS + t] = v - lse;
}

// ---------------- launch ----------------
extern "C" void kernel_launch(void* const* d_in, const int* in_sizes, int n_in,
                              void* d_out, int out_size) {
    const float* x  = (const float*)d_in[0];
    const void* ei1 = d_in[1];
    const void* ei2 = d_in[2];

    // Locate W1 by its unique element count (robust to whether size1/size2
    // scalars appear in the input list).
    int wi = 3;
    for (int i = 3; i < n_in; i++) {
        if (in_sizes[i] == F_IN * HC) { wi = i; break; }
    }
    const float* W1    = (const float*)d_in[wi];
    const float* asrc1 = (const float*)d_in[wi + 1];
    const float* adst1 = (const float*)d_in[wi + 2];
    const float* b1    = (const float*)d_in[wi + 3];
    const float* W2    = (const float*)d_in[wi + 4];
    const float* asrc2 = (const float*)d_in[wi + 5];
    const float* adst2 = (const float*)d_in[wi + 6];
    const float* b2    = (const float*)d_in[wi + 7];
    float* out = (float*)d_out;

    k_detect<<<1, 1>>>((const int*)ei1);
    k_zero<<<(N1 * HC + 255) / 256, 256>>>();
    k_gemm1<<<N0 / 64, 256>>>(x, W1);
    k_att1<<<(N0 * H1 + 255) / 256, 256>>>(asrc1, adst1);
    k_e1max<<<(ET1 + 127) / 128, 128>>>(ei1);
    k_e1sum<<<(ET1 + 127) / 128, 128>>>();
    k_rcp1<<<(N1 * H1 + 255) / 256, 256>>>();
    k_e1scat<<<(int)(((long)ET1 * 16 + 255) / 256), 256>>>();
    k_elu<<<(N1 * HC + 255) / 256, 256>>>(b1);
    k_gemm2<<<N1 / 32, 256>>>(W2);
    k_att2<<<(N1 + 255) / 256, 256>>>(asrc2, adst2);
    k_e2max<<<(ET2 + 127) / 128, 128>>>(ei2);
    k_e2sum<<<(ET2 + 127) / 128, 128>>>();
    k_rcp2<<<(N2 + 255) / 256, 256>>>();
    k_e2scat<<<(ET2 * NCLS + 255) / 256, 256>>>();
    k_logsm<<<N2, 64>>>(b2, out);
    (void)out_size;
}